// round 3
// baseline (speedup 1.0000x reference)
#include <cuda_runtime.h>
#include <cstdint>

// ---------------- problem constants ----------------
#define BB 4
#define NN 6
#define DD 41
#define FH 16
#define FW 44
#define CC 64
#define NX 200
#define NY 200
#define NP (BB*NN*DD*FH*FW)        // 692736 points
#define PTS_PER_BN (DD*FH*FW)      // 28864
#define SPATIAL (NX*NY)            // 40000

// scratch accumulator, channel-last: (B, NX, NY, C).
// INVARIANT: zero at entry to kernel_launch. Zero-initialized at module load;
// transpose_zero_kernel re-zeroes it after reading, so every full launch
// restores the invariant (graph replays stay deterministic).
__device__ __align__(16) float g_scratch[BB * SPATIAL * CC];
// per-(b,n) params: comb[9], invPostRots[9], post_trans[3], trans[3] = 24 floats
__device__ float g_params[BB * NN * 24];
// per-point precomputed scratch float-offset (or -1 if culled)
__device__ int g_idx[NP];

// ---------------- 3x3 inverse (adjugate) ----------------
__device__ __forceinline__ void inv3(const float* m, float* o) {
    float a=m[0],b=m[1],c=m[2],d=m[3],e=m[4],f=m[5],g=m[6],h=m[7],i=m[8];
    float A  =  (e*i - f*h);
    float Bm = -(d*i - f*g);
    float Cm =  (d*h - e*g);
    float det = a*A + b*Bm + c*Cm;
    float inv = 1.0f / det;
    o[0] =  A*inv;
    o[1] = -(b*i - c*h)*inv;
    o[2] =  (b*f - c*e)*inv;
    o[3] =  Bm*inv;
    o[4] =  (a*i - c*g)*inv;
    o[5] = -(a*f - c*d)*inv;
    o[6] =  Cm*inv;
    o[7] = -(a*h - b*g)*inv;
    o[8] =  (a*e - b*d)*inv;
}

// ---------------- precompute per-(b,n) transforms ----------------
__global__ void precompute_kernel(const float* __restrict__ rots,
                                  const float* __restrict__ intrins,
                                  const float* __restrict__ post_rots,
                                  const float* __restrict__ trans,
                                  const float* __restrict__ post_trans) {
    int i = threadIdx.x;
    if (i >= BB*NN) return;
    const float* R  = rots      + i*9;
    const float* K  = intrins   + i*9;
    const float* PR = post_rots + i*9;

    float iK[9], iPR[9], comb[9];
    inv3(K, iK);
    inv3(PR, iPR);
    #pragma unroll
    for (int r = 0; r < 3; r++)
        #pragma unroll
        for (int c = 0; c < 3; c++)
            comb[r*3+c] = R[r*3+0]*iK[0*3+c] + R[r*3+1]*iK[1*3+c] + R[r*3+2]*iK[2*3+c];

    float* o = g_params + i*24;
    #pragma unroll
    for (int k = 0; k < 9; k++) o[k]   = comb[k];
    #pragma unroll
    for (int k = 0; k < 9; k++) o[9+k] = iPR[k];
    o[18] = post_trans[i*3+0]; o[19] = post_trans[i*3+1]; o[20] = post_trans[i*3+2];
    o[21] = trans[i*3+0];      o[22] = trans[i*3+1];      o[23] = trans[i*3+2];
}

// ---------------- per-point geometry -> voxel offset ----------------
__global__ void idx_kernel() {
    int p = blockIdx.x * blockDim.x + threadIdx.x;
    if (p >= NP) return;

    int bn  = p / PTS_PER_BN;
    int rem = p - bn * PTS_PER_BN;
    int d   = rem / (FH*FW);
    int hw  = rem - d * (FH*FW);
    int h   = hw / FW;
    int w   = hw - h * FW;
    int b   = bn / NN;

    const float* prm = g_params + bn*24;

    float u   = (float)w * (351.0f / 43.0f);
    float v   = (float)h * (127.0f / 15.0f);
    float dep = 4.0f + (float)d;

    float px = u   - prm[18];
    float py = v   - prm[19];
    float pz = dep - prm[20];
    float qx = prm[9]*px  + prm[10]*py + prm[11]*pz;
    float qy = prm[12]*px + prm[13]*py + prm[14]*pz;
    float qz = prm[15]*px + prm[16]*py + prm[17]*pz;
    float sx = qx * qz;
    float sy = qy * qz;
    float sz = qz;
    float gx = prm[0]*sx + prm[1]*sy + prm[2]*sz + prm[21];
    float gy = prm[3]*sx + prm[4]*sy + prm[5]*sz + prm[22];
    float gz = prm[6]*sx + prm[7]*sy + prm[8]*sz + prm[23];

    int ix = (int)((gx + 50.0f) / 0.5f);
    int iy = (int)((gy + 50.0f) / 0.5f);
    int iz = (int)((gz + 10.0f) / 20.0f);

    int idx = -1;
    if (ix >= 0 && ix < NX && iy >= 0 && iy < NY && iz == 0)
        idx = ((b*NX + ix)*NY + iy) * CC;
    g_idx[p] = idx;
}

// ---------------- pure scatter-add (16 threads per point) ----------------
__global__ void scatter_kernel(const float* __restrict__ x) {
    int gtid = blockIdx.x * blockDim.x + threadIdx.x;
    int p    = gtid >> 4;          // point index
    int lane = gtid & 15;          // float4 slot within 64-channel row

    int idx = __ldg(g_idx + p);    // 16 lanes hit the same 4B -> 1 sector
    if (idx < 0) return;

    float4 val = __ldg(reinterpret_cast<const float4*>(x + (size_t)p * CC) + lane);
    float* dst = g_scratch + (size_t)idx + lane*4;
    asm volatile("red.global.add.v4.f32 [%0], {%1, %2, %3, %4};"
                 :: "l"(dst), "f"(val.x), "f"(val.y), "f"(val.z), "f"(val.w)
                 : "memory");
}

// ---------------- transpose (B, S, C) -> (B, C, S) + re-zero scratch ----------------
// One block owns a full 32-spatial x 64-channel scratch tile (exclusive),
// so it can safely zero it after reading.
__global__ void transpose_zero_kernel(float* __restrict__ out) {
    __shared__ float tile[CC][33];
    int b   = blockIdx.y;
    int s0  = blockIdx.x * 32;
    int tid = threadIdx.x;           // 0..255

    float4* src = reinterpret_cast<float4*>(g_scratch + ((size_t)b * SPATIAL + s0) * CC);
    const float4 z4 = make_float4(0.f, 0.f, 0.f, 0.f);
    #pragma unroll
    for (int i = 0; i < 2; i++) {
        int j  = tid + i*256;        // 0..511 float4s (32 s-rows x 16 float4)
        int sl = j >> 4;             // spatial within tile
        int c4 = j & 15;             // float4 within channel row
        float4 v = src[j];
        tile[c4*4+0][sl] = v.x;
        tile[c4*4+1][sl] = v.y;
        tile[c4*4+2][sl] = v.z;
        tile[c4*4+3][sl] = v.w;
        src[j] = z4;                 // restore zero-invariant (L2-hit, line just read)
    }
    __syncthreads();

    float* dst = out + (size_t)b * CC * SPATIAL + s0;
    int lanes = tid & 31;
    int wrp   = tid >> 5;            // 0..7
    #pragma unroll
    for (int i = 0; i < 8; i++) {
        int c = wrp + i*8;
        dst[(size_t)c * SPATIAL + lanes] = tile[c][lanes];
    }
}

// ---------------- launch ----------------
extern "C" void kernel_launch(void* const* d_in, const int* in_sizes, int n_in,
                              void* d_out, int out_size) {
    const float* x          = (const float*)d_in[0];
    const float* rots       = (const float*)d_in[1];
    const float* trans      = (const float*)d_in[2];
    const float* intrins    = (const float*)d_in[3];
    const float* post_rots  = (const float*)d_in[4];
    const float* post_trans = (const float*)d_in[5];
    float* out = (float*)d_out;

    precompute_kernel<<<1, 32>>>(rots, intrins, post_rots, trans, post_trans);

    // one thread per point: 692736 / 256 = 2706 blocks
    idx_kernel<<<2706, 256>>>();

    // 16 lanes per point: 692736 * 16 = 11,083,776 threads / 256 = 43296 blocks
    scatter_kernel<<<43296, 256>>>(x);

    // S=40000 -> 1250 tiles of 32 spatial x full 64 channels; B=4
    transpose_zero_kernel<<<dim3(1250, 4), 256>>>(out);
}

// round 4
// speedup vs baseline: 1.9618x; 1.9618x over previous
#include <cuda_runtime.h>
#include <cstdint>

// ---------------- problem constants ----------------
#define BB 4
#define NN 6
#define DD 41
#define FH 16
#define FW 44
#define CC 64
#define NX 200
#define NY 200
#define NP (BB*NN*DD*FH*FW)        // 692736 points
#define PTS_PER_BN (DD*FH*FW)      // 28864
#define SPATIAL (NX*NY)            // 40000

// scratch accumulator, channel-last: (B, NX, NY, C)
__device__ __align__(16) float g_scratch[BB * SPATIAL * CC];
// per-(b,n) params: comb[9], invPostRots[9], post_trans[3], trans[3] = 24 floats
__device__ float g_params[BB * NN * 24];
// per-point precomputed scratch float-offset (or -1 if culled)
__device__ int g_idx[NP];

// ---------------- 3x3 inverse (adjugate) ----------------
__device__ __forceinline__ void inv3(const float* m, float* o) {
    float a=m[0],b=m[1],c=m[2],d=m[3],e=m[4],f=m[5],g=m[6],h=m[7],i=m[8];
    float A  =  (e*i - f*h);
    float Bm = -(d*i - f*g);
    float Cm =  (d*h - e*g);
    float det = a*A + b*Bm + c*Cm;
    float inv = 1.0f / det;
    o[0] =  A*inv;
    o[1] = -(b*i - c*h)*inv;
    o[2] =  (b*f - c*e)*inv;
    o[3] =  Bm*inv;
    o[4] =  (a*i - c*g)*inv;
    o[5] = -(a*f - c*d)*inv;
    o[6] =  Cm*inv;
    o[7] = -(a*h - b*g)*inv;
    o[8] =  (a*e - b*d)*inv;
}

// ---------------- precompute per-(b,n) transforms ----------------
__global__ void precompute_kernel(const float* __restrict__ rots,
                                  const float* __restrict__ intrins,
                                  const float* __restrict__ post_rots,
                                  const float* __restrict__ trans,
                                  const float* __restrict__ post_trans) {
    int i = threadIdx.x;
    if (i >= BB*NN) return;
    const float* R  = rots      + i*9;
    const float* K  = intrins   + i*9;
    const float* PR = post_rots + i*9;

    float iK[9], iPR[9], comb[9];
    inv3(K, iK);
    inv3(PR, iPR);
    #pragma unroll
    for (int r = 0; r < 3; r++)
        #pragma unroll
        for (int c = 0; c < 3; c++)
            comb[r*3+c] = R[r*3+0]*iK[0*3+c] + R[r*3+1]*iK[1*3+c] + R[r*3+2]*iK[2*3+c];

    float* o = g_params + i*24;
    #pragma unroll
    for (int k = 0; k < 9; k++) o[k]   = comb[k];
    #pragma unroll
    for (int k = 0; k < 9; k++) o[9+k] = iPR[k];
    o[18] = post_trans[i*3+0]; o[19] = post_trans[i*3+1]; o[20] = post_trans[i*3+2];
    o[21] = trans[i*3+0];      o[22] = trans[i*3+1];      o[23] = trans[i*3+2];
}

// ---------------- zero the scratch accumulator ----------------
__global__ void zero_kernel() {
    int idx = blockIdx.x * blockDim.x + threadIdx.x;   // float4 index
    float4 z = make_float4(0.f, 0.f, 0.f, 0.f);
    reinterpret_cast<float4*>(g_scratch)[idx] = z;
}

// ---------------- per-point geometry -> voxel offset ----------------
__global__ void idx_kernel() {
    int p = blockIdx.x * blockDim.x + threadIdx.x;
    if (p >= NP) return;

    int bn  = p / PTS_PER_BN;
    int rem = p - bn * PTS_PER_BN;
    int d   = rem / (FH*FW);
    int hw  = rem - d * (FH*FW);
    int h   = hw / FW;
    int w   = hw - h * FW;
    int b   = bn / NN;

    const float* prm = g_params + bn*24;

    float u   = (float)w * (351.0f / 43.0f);
    float v   = (float)h * (127.0f / 15.0f);
    float dep = 4.0f + (float)d;

    float px = u   - prm[18];
    float py = v   - prm[19];
    float pz = dep - prm[20];
    float qx = prm[9]*px  + prm[10]*py + prm[11]*pz;
    float qy = prm[12]*px + prm[13]*py + prm[14]*pz;
    float qz = prm[15]*px + prm[16]*py + prm[17]*pz;
    float sx = qx * qz;
    float sy = qy * qz;
    float sz = qz;
    float gx = prm[0]*sx + prm[1]*sy + prm[2]*sz + prm[21];
    float gy = prm[3]*sx + prm[4]*sy + prm[5]*sz + prm[22];
    float gz = prm[6]*sx + prm[7]*sy + prm[8]*sz + prm[23];

    int ix = (int)((gx + 50.0f) / 0.5f);
    int iy = (int)((gy + 50.0f) / 0.5f);
    int iz = (int)((gz + 10.0f) / 20.0f);

    int idx = -1;
    if (ix >= 0 && ix < NX && iy >= 0 && iy < NY && iz == 0)
        idx = ((b*NX + ix)*NY + iy) * CC;
    g_idx[p] = idx;
}

// ---------------- pure scatter-add (16 threads per point) ----------------
__global__ void scatter_kernel(const float* __restrict__ x) {
    int gtid = blockIdx.x * blockDim.x + threadIdx.x;
    int p    = gtid >> 4;          // point index
    int lane = gtid & 15;          // float4 slot within 64-channel row

    int idx = __ldg(g_idx + p);    // 16 lanes hit the same 4B -> 1 sector
    if (idx < 0) return;

    float4 val = __ldg(reinterpret_cast<const float4*>(x + (size_t)p * CC) + lane);
    float* dst = g_scratch + (size_t)idx + lane*4;
    asm volatile("red.global.add.v4.f32 [%0], {%1, %2, %3, %4};"
                 :: "l"(dst), "f"(val.x), "f"(val.y), "f"(val.z), "f"(val.w)
                 : "memory");
}

// ---------------- transpose (B, S, C) -> (B, C, S) ----------------
__global__ void transpose_kernel(float* __restrict__ out) {
    __shared__ float tile[32][33];
    int b  = blockIdx.z;
    int c0 = blockIdx.y * 32;
    int s0 = blockIdx.x * 32;
    int tx = threadIdx.x;        // 0..31
    int ty = threadIdx.y;        // 0..7

    const float* src = g_scratch + (size_t)b * SPATIAL * CC;
    #pragma unroll
    for (int i = 0; i < 32; i += 8) {
        int s = s0 + ty + i;
        tile[ty + i][tx] = src[(size_t)s * CC + c0 + tx];
    }
    __syncthreads();
    float* dst = out + (size_t)b * CC * SPATIAL;
    #pragma unroll
    for (int i = 0; i < 32; i += 8) {
        int c = c0 + ty + i;
        dst[(size_t)c * SPATIAL + s0 + tx] = tile[tx][ty + i];
    }
}

// ---------------- launch ----------------
extern "C" void kernel_launch(void* const* d_in, const int* in_sizes, int n_in,
                              void* d_out, int out_size) {
    const float* x          = (const float*)d_in[0];
    const float* rots       = (const float*)d_in[1];
    const float* trans      = (const float*)d_in[2];
    const float* intrins    = (const float*)d_in[3];
    const float* post_rots  = (const float*)d_in[4];
    const float* post_trans = (const float*)d_in[5];
    float* out = (float*)d_out;

    precompute_kernel<<<1, 32>>>(rots, intrins, post_rots, trans, post_trans);

    // scratch = 10,240,000 floats = 2,560,000 float4
    zero_kernel<<<10000, 256>>>();

    // one thread per point: 692736 / 256 = 2706 blocks
    idx_kernel<<<2706, 256>>>();

    // 16 lanes per point: 692736 * 16 = 11,083,776 threads / 256 = 43296 blocks
    scatter_kernel<<<43296, 256>>>(x);

    // S=40000 -> 1250 tiles of 32; C=64 -> 2 tiles; B=4
    transpose_kernel<<<dim3(1250, 2, 4), dim3(32, 8)>>>(out);
}

// round 5
// speedup vs baseline: 2.1042x; 1.0726x over previous
#include <cuda_runtime.h>
#include <cstdint>

// ---------------- problem constants ----------------
#define BB 4
#define NN 6
#define DD 41
#define FH 16
#define FW 44
#define CC 64
#define NX 200
#define NY 200
#define PTS_PER_BN (DD*FH*FW)      // 28864
#define RAYS_PER_BN (FH*FW)        // 704
#define SPATIAL (NX*NY)            // 40000

// ---------------- 3x3 inverse (adjugate) ----------------
__device__ __forceinline__ void inv3(const float* m, float* o) {
    float a=m[0],b=m[1],c=m[2],d=m[3],e=m[4],f=m[5],g=m[6],h=m[7],i=m[8];
    float A  =  (e*i - f*h);
    float Bm = -(d*i - f*g);
    float Cm =  (d*h - e*g);
    float det = a*A + b*Bm + c*Cm;
    float inv = 1.0f / det;
    o[0] =  A*inv;
    o[1] = -(b*i - c*h)*inv;
    o[2] =  (b*f - c*e)*inv;
    o[3] =  Bm*inv;
    o[4] =  (a*i - c*g)*inv;
    o[5] = -(a*f - c*d)*inv;
    o[6] =  Cm*inv;
    o[7] = -(a*h - b*g)*inv;
    o[8] =  (a*e - b*d)*inv;
}

// ---------------- zero the output ----------------
__global__ void zero_out_kernel(float4* __restrict__ out4) {
    int idx = blockIdx.x * blockDim.x + threadIdx.x;   // float4 index
    out4[idx] = make_float4(0.f, 0.f, 0.f, 0.f);
}

// ---------------- fused geometry + run-accumulate + scatter ----------------
// One 16-lane group walks one camera ray through all 41 depths.
// Lane l owns channels [4l, 4l+4). Consecutive depths hitting the same voxel
// are pre-summed in registers; each run is flushed with 4 scalar atomicAdds
// per lane directly into the (B, C, NX, NY) output.
__global__ void __launch_bounds__(256) ray_scatter_kernel(
        const float* __restrict__ x,
        const float* __restrict__ rots,
        const float* __restrict__ intrins,
        const float* __restrict__ post_rots,
        const float* __restrict__ trans,
        const float* __restrict__ post_trans,
        float* __restrict__ out) {
    __shared__ float prm[24];

    // 44 blocks per (b,n); each block covers 16 consecutive rays of one bn.
    int bn = blockIdx.x / (RAYS_PER_BN / 16);
    int blk_in_bn = blockIdx.x - bn * (RAYS_PER_BN / 16);

    if (threadIdx.x == 0) {
        float iK[9], iPR[9];
        inv3(intrins + bn*9, iK);
        inv3(post_rots + bn*9, iPR);
        const float* R = rots + bn*9;
        #pragma unroll
        for (int r = 0; r < 3; r++)
            #pragma unroll
            for (int c = 0; c < 3; c++)
                prm[r*3+c] = R[r*3+0]*iK[0*3+c] + R[r*3+1]*iK[1*3+c] + R[r*3+2]*iK[2*3+c];
        #pragma unroll
        for (int k = 0; k < 9; k++) prm[9+k] = iPR[k];
        prm[18] = post_trans[bn*3+0];
        prm[19] = post_trans[bn*3+1];
        prm[20] = post_trans[bn*3+2];
        prm[21] = trans[bn*3+0];
        prm[22] = trans[bn*3+1];
        prm[23] = trans[bn*3+2];
    }
    __syncthreads();

    int grp    = threadIdx.x >> 4;     // ray within block, 0..15
    int lane16 = threadIdx.x & 15;     // float4 slot within the 64-channel row
    int hw     = blk_in_bn * 16 + grp; // ray within bn, 0..703
    int h      = hw / FW;
    int w      = hw - h * FW;
    int b      = bn / NN;

    // copy params to registers (loop-invariant)
    float c00=prm[0], c01=prm[1], c02=prm[2];
    float c10=prm[3], c11=prm[4], c12=prm[5];
    float c20=prm[6], c21=prm[7], c22=prm[8];
    float t0=prm[21], t1=prm[22], t2=prm[23];

    float u = (float)w * (351.0f / 43.0f);
    float v = (float)h * (127.0f / 15.0f);
    float px  = u    - prm[18];
    float py  = v    - prm[19];
    float pz0 = 4.0f - prm[20];

    // q = invPostRots @ (px, py, pz); affine in depth -> incremental
    float qx  = prm[ 9]*px + prm[10]*py + prm[11]*pz0;
    float qy  = prm[12]*px + prm[13]*py + prm[14]*pz0;
    float qz  = prm[15]*px + prm[16]*py + prm[17]*pz0;
    float dqx = prm[11], dqy = prm[14], dqz = prm[17];

    int obase = b * (CC * SPATIAL);
    const float4* xr = reinterpret_cast<const float4*>(x)
                       + (size_t)(bn * PTS_PER_BN + hw) * 16 + lane16;

    int cur = -1;
    float4 acc = make_float4(0.f, 0.f, 0.f, 0.f);

    #pragma unroll 1
    for (int d = 0; d < DD; d++) {
        float sx = qx * qz;
        float sy = qy * qz;
        float gx = c00*sx + c01*sy + c02*qz + t0;
        float gy = c10*sx + c11*sy + c12*qz + t1;
        float gz = c20*sx + c21*sy + c22*qz + t2;

        int ix = (int)((gx + 50.0f) / 0.5f);
        int iy = (int)((gy + 50.0f) / 0.5f);
        int iz = (int)((gz + 10.0f) / 20.0f);

        int o = -1;
        if (ix >= 0 && ix < NX && iy >= 0 && iy < NY && iz == 0)
            o = obase + ix * NY + iy;

        if (o != cur) {
            if (cur >= 0) {
                float* dp = out + cur + (size_t)(lane16 * 4) * SPATIAL;
                atomicAdd(dp,               acc.x);
                atomicAdd(dp +   SPATIAL,   acc.y);
                atomicAdd(dp + 2*SPATIAL,   acc.z);
                atomicAdd(dp + 3*SPATIAL,   acc.w);
            }
            acc = make_float4(0.f, 0.f, 0.f, 0.f);
            cur = o;
        }
        if (o >= 0) {
            float4 vv = __ldg(xr + (size_t)d * (RAYS_PER_BN * 16));
            acc.x += vv.x; acc.y += vv.y; acc.z += vv.z; acc.w += vv.w;
        }

        qx += dqx; qy += dqy; qz += dqz;
    }
    if (cur >= 0) {
        float* dp = out + cur + (size_t)(lane16 * 4) * SPATIAL;
        atomicAdd(dp,             acc.x);
        atomicAdd(dp +   SPATIAL, acc.y);
        atomicAdd(dp + 2*SPATIAL, acc.z);
        atomicAdd(dp + 3*SPATIAL, acc.w);
    }
}

// ---------------- launch ----------------
extern "C" void kernel_launch(void* const* d_in, const int* in_sizes, int n_in,
                              void* d_out, int out_size) {
    const float* x          = (const float*)d_in[0];
    const float* rots       = (const float*)d_in[1];
    const float* trans      = (const float*)d_in[2];
    const float* intrins    = (const float*)d_in[3];
    const float* post_rots  = (const float*)d_in[4];
    const float* post_trans = (const float*)d_in[5];
    float* out = (float*)d_out;

    // out = 4*64*200*200 = 10,240,000 floats = 2,560,000 float4
    zero_out_kernel<<<10000, 256>>>((float4*)out);

    // 16896 rays * 16 lanes = 270,336 threads = 1056 blocks of 256
    ray_scatter_kernel<<<1056, 256>>>(x, rots, intrins, post_rots, trans,
                                      post_trans, out);
}

// round 6
// speedup vs baseline: 2.1898x; 1.0407x over previous
#include <cuda_runtime.h>
#include <cstdint>

// ---------------- problem constants ----------------
#define BB 4
#define NN 6
#define DD 41
#define FH 16
#define FW 44
#define CC 64
#define NX 200
#define NY 200
#define NP (BB*NN*DD*FH*FW)        // 692736
#define PTS_PER_BN (DD*FH*FW)      // 28864
#define RAYS_PER_BN (FH*FW)        // 704
#define NRAYS (BB*NN*RAYS_PER_BN)  // 16896
#define SPATIAL (NX*NY)            // 40000

// compacted run list: rec.x = p_start | (count<<20), rec.y = out offset (floats)
__device__ int2 g_runs[NP];
__device__ int  g_count;

// ---------------- 3x3 inverse (adjugate) ----------------
__device__ __forceinline__ void inv3(const float* m, float* o) {
    float a=m[0],b=m[1],c=m[2],d=m[3],e=m[4],f=m[5],g=m[6],h=m[7],i=m[8];
    float A  =  (e*i - f*h);
    float Bm = -(d*i - f*g);
    float Cm =  (d*h - e*g);
    float det = a*A + b*Bm + c*Cm;
    float inv = 1.0f / det;
    o[0] =  A*inv;
    o[1] = -(b*i - c*h)*inv;
    o[2] =  (b*f - c*e)*inv;
    o[3] =  Bm*inv;
    o[4] =  (a*i - c*g)*inv;
    o[5] = -(a*f - c*d)*inv;
    o[6] =  Cm*inv;
    o[7] = -(a*h - b*g)*inv;
    o[8] =  (a*e - b*d)*inv;
}

// ---------------- zero output + run counter ----------------
__global__ void zero_out_kernel(float4* __restrict__ out4) {
    int idx = blockIdx.x * blockDim.x + threadIdx.x;   // float4 index
    out4[idx] = make_float4(0.f, 0.f, 0.f, 0.f);
    if (idx == 0) g_count = 0;
}

// ---------------- per-ray geometry walk -> compacted run list ----------------
// One thread per camera ray. Walks all 41 depths with incremental geometry;
// consecutive depths landing in the same voxel form a run. Runs are appended
// to g_runs with warp-aggregated atomics (one leader atomicAdd per flush step).
__global__ void __launch_bounds__(256) run_kernel(
        const float* __restrict__ rots,
        const float* __restrict__ intrins,
        const float* __restrict__ post_rots,
        const float* __restrict__ trans,
        const float* __restrict__ post_trans) {
    int ray  = blockIdx.x * blockDim.x + threadIdx.x;   // 0..16895
    int lane = threadIdx.x & 31;
    int bn   = ray / RAYS_PER_BN;
    int hw   = ray - bn * RAYS_PER_BN;
    int h    = hw / FW;
    int w    = hw - h * FW;
    int b    = bn / NN;

    // per-thread transform computation (cheap; 16896 threads total)
    float iK[9], iPR[9], cmb[9];
    inv3(intrins + bn*9, iK);
    inv3(post_rots + bn*9, iPR);
    const float* R = rots + bn*9;
    #pragma unroll
    for (int r = 0; r < 3; r++)
        #pragma unroll
        for (int c = 0; c < 3; c++)
            cmb[r*3+c] = R[r*3+0]*iK[0*3+c] + R[r*3+1]*iK[1*3+c] + R[r*3+2]*iK[2*3+c];
    float t0 = trans[bn*3+0], t1 = trans[bn*3+1], t2 = trans[bn*3+2];
    float pt0 = post_trans[bn*3+0], pt1 = post_trans[bn*3+1], pt2 = post_trans[bn*3+2];

    float u = (float)w * (351.0f / 43.0f);
    float v = (float)h * (127.0f / 15.0f);
    float px  = u    - pt0;
    float py  = v    - pt1;
    float pz0 = 4.0f - pt2;

    float qx  = iPR[0]*px + iPR[1]*py + iPR[2]*pz0;
    float qy  = iPR[3]*px + iPR[4]*py + iPR[5]*pz0;
    float qz  = iPR[6]*px + iPR[7]*py + iPR[8]*pz0;
    float dqx = iPR[2], dqy = iPR[5], dqz = iPR[8];

    int obase = b * (CC * SPATIAL);
    int cur = -1;
    int curStart = 0;

    #pragma unroll 1
    for (int d = 0; d < DD; d++) {
        float sx = qx * qz;
        float sy = qy * qz;
        float gx = cmb[0]*sx + cmb[1]*sy + cmb[2]*qz + t0;
        float gy = cmb[3]*sx + cmb[4]*sy + cmb[5]*qz + t1;
        float gz = cmb[6]*sx + cmb[7]*sy + cmb[8]*qz + t2;

        int ix = (int)((gx + 50.0f) / 0.5f);
        int iy = (int)((gy + 50.0f) / 0.5f);
        int iz = (int)((gz + 10.0f) / 20.0f);

        int o = -1;
        if (ix >= 0 && ix < NX && iy >= 0 && iy < NY && iz == 0)
            o = obase + ix * NY + iy;

        // warp-aggregated run emission
        bool flush = (o != cur) && (cur >= 0);
        unsigned bal = __ballot_sync(0xffffffffu, flush);
        if (bal) {
            int leader = __ffs(bal) - 1;
            int base = 0;
            if (lane == leader) base = atomicAdd(&g_count, __popc(bal));
            base = __shfl_sync(0xffffffffu, base, leader);
            if (flush) {
                int slot = base + __popc(bal & ((1u << lane) - 1u));
                int p0   = (bn*DD + curStart) * RAYS_PER_BN + hw;
                g_runs[slot] = make_int2(p0 | ((d - curStart) << 20), cur);
            }
        }
        if (o != cur) { cur = o; curStart = d; }

        qx += dqx; qy += dqy; qz += dqz;
    }

    // final flush
    {
        bool flush = (cur >= 0);
        unsigned bal = __ballot_sync(0xffffffffu, flush);
        if (bal) {
            int leader = __ffs(bal) - 1;
            int base = 0;
            if (lane == leader) base = atomicAdd(&g_count, __popc(bal));
            base = __shfl_sync(0xffffffffu, base, leader);
            if (flush) {
                int slot = base + __popc(bal & ((1u << lane) - 1u));
                int p0   = (bn*DD + curStart) * RAYS_PER_BN + hw;
                g_runs[slot] = make_int2(p0 | ((DD - curStart) << 20), cur);
            }
        }
    }
}

// ---------------- persistent run scatter ----------------
// One warp per run: lane l accumulates channels (2l, 2l+1) over the run's
// depths (float2 loads, 256B/warp coalesced), then 2 scalar atomicAdds into
// the final (B, C, NX, NY) output.
__global__ void __launch_bounds__(256) scatter_runs_kernel(
        const float* __restrict__ x,
        float* __restrict__ out) {
    int wid   = (blockIdx.x * blockDim.x + threadIdx.x) >> 5;
    int lane  = threadIdx.x & 31;
    int nwarp = (gridDim.x * blockDim.x) >> 5;
    int nruns = g_count;

    for (int r = wid; r < nruns; r += nwarp) {
        int2 rec = g_runs[r];
        int p0   = rec.x & 0xFFFFF;
        int cnt  = rec.x >> 20;
        int off  = rec.y;

        const float2* src = reinterpret_cast<const float2*>(x)
                            + (size_t)p0 * (CC/2) + lane;
        float2 acc = make_float2(0.f, 0.f);
        for (int j = 0; j < cnt; j++) {
            float2 vv = __ldg(src + (size_t)j * (RAYS_PER_BN * (CC/2)));
            acc.x += vv.x; acc.y += vv.y;
        }
        float* dp = out + off + (size_t)(2*lane) * SPATIAL;
        atomicAdd(dp,           acc.x);
        atomicAdd(dp + SPATIAL, acc.y);
    }
}

// ---------------- launch ----------------
extern "C" void kernel_launch(void* const* d_in, const int* in_sizes, int n_in,
                              void* d_out, int out_size) {
    const float* x          = (const float*)d_in[0];
    const float* rots       = (const float*)d_in[1];
    const float* trans      = (const float*)d_in[2];
    const float* intrins    = (const float*)d_in[3];
    const float* post_rots  = (const float*)d_in[4];
    const float* post_trans = (const float*)d_in[5];
    float* out = (float*)d_out;

    // out = 10,240,000 floats = 2,560,000 float4
    zero_out_kernel<<<10000, 256>>>((float4*)out);

    // 16896 rays, 1 thread each
    run_kernel<<<NRAYS/256, 256>>>(rots, intrins, post_rots, trans, post_trans);

    // persistent: 1184 blocks (8 per SM on 148 SMs), 8 warps each
    scatter_runs_kernel<<<1184, 256>>>(x, out);
}

// round 7
// speedup vs baseline: 2.9091x; 1.3285x over previous
#include <cuda_runtime.h>
#include <cstdint>

// ---------------- problem constants ----------------
#define BB 4
#define NN 6
#define DD 41
#define FH 16
#define FW 44
#define CC 64
#define NX 200
#define NY 200
#define NP (BB*NN*DD*FH*FW)        // 692736
#define RAYS_PER_BN (FH*FW)        // 704
#define NRAYS (BB*NN*RAYS_PER_BN)  // 16896
#define NWARPS (NRAYS/32)          // 528 geometry warps
#define RUNS_PER_WARP (32*DD)      // 1312 ; 528*1312 == NP exactly
#define SPATIAL (NX*NY)            // 40000

// run records, one private region per geometry warp:
// rec.x = p_start | (count<<20), rec.y = output offset (floats)
__device__ int2 g_runs[NP];
__device__ int  g_warp_count[NWARPS];

// ---------------- 3x3 inverse (adjugate) ----------------
__device__ __forceinline__ void inv3(const float* m, float* o) {
    float a=m[0],b=m[1],c=m[2],d=m[3],e=m[4],f=m[5],g=m[6],h=m[7],i=m[8];
    float A  =  (e*i - f*h);
    float Bm = -(d*i - f*g);
    float Cm =  (d*h - e*g);
    float det = a*A + b*Bm + c*Cm;
    float inv = 1.0f / det;
    o[0] =  A*inv;
    o[1] = -(b*i - c*h)*inv;
    o[2] =  (b*f - c*e)*inv;
    o[3] =  Bm*inv;
    o[4] =  (a*i - c*g)*inv;
    o[5] = -(a*f - c*d)*inv;
    o[6] =  Cm*inv;
    o[7] = -(a*h - b*g)*inv;
    o[8] =  (a*e - b*d)*inv;
}

// ---------------- zero output ----------------
__global__ void zero_out_kernel(float4* __restrict__ out4) {
    int idx = blockIdx.x * blockDim.x + threadIdx.x;   // float4 index
    out4[idx] = make_float4(0.f, 0.f, 0.f, 0.f);
}

// ---------------- per-ray geometry walk -> private run regions ----------------
// One thread per camera ray; warp-local ballot/popc slot assignment, NO global
// atomics. Each warp writes its runs into its own 1312-slot region of g_runs.
__global__ void __launch_bounds__(256) run_kernel(
        const float* __restrict__ rots,
        const float* __restrict__ intrins,
        const float* __restrict__ post_rots,
        const float* __restrict__ trans,
        const float* __restrict__ post_trans) {
    int ray  = blockIdx.x * blockDim.x + threadIdx.x;   // 0..16895
    int lane = threadIdx.x & 31;
    int wid  = ray >> 5;                                // 0..527
    int bn   = ray / RAYS_PER_BN;
    int hw   = ray - bn * RAYS_PER_BN;
    int h    = hw / FW;
    int w    = hw - h * FW;
    int b    = bn / NN;

    float iK[9], iPR[9], cmb[9];
    inv3(intrins + bn*9, iK);
    inv3(post_rots + bn*9, iPR);
    const float* R = rots + bn*9;
    #pragma unroll
    for (int r = 0; r < 3; r++)
        #pragma unroll
        for (int c = 0; c < 3; c++)
            cmb[r*3+c] = R[r*3+0]*iK[0*3+c] + R[r*3+1]*iK[1*3+c] + R[r*3+2]*iK[2*3+c];
    float t0 = trans[bn*3+0], t1 = trans[bn*3+1], t2 = trans[bn*3+2];
    float pt0 = post_trans[bn*3+0], pt1 = post_trans[bn*3+1], pt2 = post_trans[bn*3+2];

    float u = (float)w * (351.0f / 43.0f);
    float v = (float)h * (127.0f / 15.0f);
    float px  = u    - pt0;
    float py  = v    - pt1;
    float pz0 = 4.0f - pt2;

    float qx  = iPR[0]*px + iPR[1]*py + iPR[2]*pz0;
    float qy  = iPR[3]*px + iPR[4]*py + iPR[5]*pz0;
    float qz  = iPR[6]*px + iPR[7]*py + iPR[8]*pz0;
    float dqx = iPR[2], dqy = iPR[5], dqz = iPR[8];

    int2* region = g_runs + wid * RUNS_PER_WARP;
    unsigned lt_mask = (1u << lane) - 1u;

    int obase = b * (CC * SPATIAL);
    int cur = -1;
    int curStart = 0;
    int wcnt = 0;                  // warp-uniform running count

    #pragma unroll 1
    for (int d = 0; d < DD; d++) {
        float sx = qx * qz;
        float sy = qy * qz;
        float gx = cmb[0]*sx + cmb[1]*sy + cmb[2]*qz + t0;
        float gy = cmb[3]*sx + cmb[4]*sy + cmb[5]*qz + t1;
        float gz = cmb[6]*sx + cmb[7]*sy + cmb[8]*qz + t2;

        int ix = (int)((gx + 50.0f) / 0.5f);
        int iy = (int)((gy + 50.0f) / 0.5f);
        int iz = (int)((gz + 10.0f) / 20.0f);

        int o = -1;
        if (ix >= 0 && ix < NX && iy >= 0 && iy < NY && iz == 0)
            o = obase + ix * NY + iy;

        bool flush = (o != cur) && (cur >= 0);
        unsigned bal = __ballot_sync(0xffffffffu, flush);
        if (flush) {
            int p0 = (bn*DD + curStart) * RAYS_PER_BN + hw;
            region[wcnt + __popc(bal & lt_mask)] =
                make_int2(p0 | ((d - curStart) << 20), cur);
        }
        wcnt += __popc(bal);
        if (o != cur) { cur = o; curStart = d; }

        qx += dqx; qy += dqy; qz += dqz;
    }

    {   // final flush
        bool flush = (cur >= 0);
        unsigned bal = __ballot_sync(0xffffffffu, flush);
        if (flush) {
            int p0 = (bn*DD + curStart) * RAYS_PER_BN + hw;
            region[wcnt + __popc(bal & lt_mask)] =
                make_int2(p0 | ((DD - curStart) << 20), cur);
        }
        wcnt += __popc(bal);
    }
    if (lane == 0) g_warp_count[wid] = wcnt;
}

// ---------------- run scatter with adjacent-offset merging ----------------
// Block s processes geometry-warp s's run segment. Each warp takes 8-run
// chunks; consecutive runs with the same output offset (adjacent rays hitting
// the same voxel) are merged in registers before the atomic flush.
// Lane l owns channels (2l, 2l+1).
#define CHUNK 8
__global__ void __launch_bounds__(256) scatter_runs_kernel(
        const float* __restrict__ x,
        float* __restrict__ out) {
    int seg  = blockIdx.x;
    int cnt  = g_warp_count[seg];
    const int2* runs = g_runs + seg * RUNS_PER_WARP;
    int wrp  = threadIdx.x >> 5;
    int lane = threadIdx.x & 31;

    for (int base = wrp * CHUNK; base < cnt; base += 8 * CHUNK) {
        int end = min(base + CHUNK, cnt);
        int curOff = -1;
        float2 acc = make_float2(0.f, 0.f);
        for (int i = base; i < end; i++) {
            int2 rec = __ldg(runs + i);
            if (rec.y != curOff) {
                if (curOff >= 0) {
                    float* dp = out + curOff + (size_t)(2*lane) * SPATIAL;
                    atomicAdd(dp,           acc.x);
                    atomicAdd(dp + SPATIAL, acc.y);
                }
                curOff = rec.y;
                acc = make_float2(0.f, 0.f);
            }
            int p0 = rec.x & 0xFFFFF;
            int c  = rec.x >> 20;
            const float2* src = reinterpret_cast<const float2*>(x)
                                + (size_t)p0 * (CC/2) + lane;
            for (int j = 0; j < c; j++) {
                float2 vv = __ldg(src + (size_t)j * (RAYS_PER_BN * (CC/2)));
                acc.x += vv.x; acc.y += vv.y;
            }
        }
        if (curOff >= 0) {
            float* dp = out + curOff + (size_t)(2*lane) * SPATIAL;
            atomicAdd(dp,           acc.x);
            atomicAdd(dp + SPATIAL, acc.y);
        }
    }
}

// ---------------- launch ----------------
extern "C" void kernel_launch(void* const* d_in, const int* in_sizes, int n_in,
                              void* d_out, int out_size) {
    const float* x          = (const float*)d_in[0];
    const float* rots       = (const float*)d_in[1];
    const float* trans      = (const float*)d_in[2];
    const float* intrins    = (const float*)d_in[3];
    const float* post_rots  = (const float*)d_in[4];
    const float* post_trans = (const float*)d_in[5];
    float* out = (float*)d_out;

    // out = 10,240,000 floats = 2,560,000 float4
    zero_out_kernel<<<10000, 256>>>((float4*)out);

    // 16896 rays, 1 thread each, atomic-free emission
    run_kernel<<<NRAYS/256, 256>>>(rots, intrins, post_rots, trans, post_trans);

    // one block per geometry-warp segment
    scatter_runs_kernel<<<NWARPS, 256>>>(x, out);
}

// round 8
// speedup vs baseline: 3.0614x; 1.0523x over previous
#include <cuda_runtime.h>
#include <cstdint>

// ---------------- problem constants ----------------
#define BB 4
#define NN 6
#define DD 41
#define FH 16
#define FW 44
#define CC 64
#define NX 200
#define NY 200
#define NP (BB*NN*DD*FH*FW)        // 692736
#define RAYS_PER_BN (FH*FW)        // 704
#define NRAYS (BB*NN*RAYS_PER_BN)  // 16896
#define NWARPS (NRAYS/32)          // 528 geometry warps
#define RUNS_PER_WARP (32*DD)      // 1312 ; 528*1312 == NP exactly
#define SPATIAL (NX*NY)            // 40000

#define RUN_BLOCKS  (NRAYS/256)    // 66
#define ZERO_BLOCKS 2500           // 2500*256*4 float4 = 2,560,000 exactly
#define ZERO_STRIDE (ZERO_BLOCKS*256)

// run records, one private region per geometry warp:
// rec.x = p_start | (count<<20), rec.y = output offset (floats)
__device__ int2 g_runs[NP];
__device__ int  g_warp_count[NWARPS];

// ---------------- 3x3 inverse (adjugate) ----------------
__device__ __forceinline__ void inv3(const float* m, float* o) {
    float a=m[0],b=m[1],c=m[2],d=m[3],e=m[4],f=m[5],g=m[6],h=m[7],i=m[8];
    float A  =  (e*i - f*h);
    float Bm = -(d*i - f*g);
    float Cm =  (d*h - e*g);
    float det = a*A + b*Bm + c*Cm;
    float inv = 1.0f / det;
    o[0] =  A*inv;
    o[1] = -(b*i - c*h)*inv;
    o[2] =  (b*f - c*e)*inv;
    o[3] =  Bm*inv;
    o[4] =  (a*i - c*g)*inv;
    o[5] = -(a*f - c*d)*inv;
    o[6] =  Cm*inv;
    o[7] = -(a*h - b*g)*inv;
    o[8] =  (a*e - b*d)*inv;
}

// ---------------- fused: ray walk (blocks 0..65) + output zero (rest) ----------------
__global__ void __launch_bounds__(256) run_zero_kernel(
        const float* __restrict__ rots,
        const float* __restrict__ intrins,
        const float* __restrict__ post_rots,
        const float* __restrict__ trans,
        const float* __restrict__ post_trans,
        float4* __restrict__ out4) {
    if (blockIdx.x >= RUN_BLOCKS) {
        // ---- zero path: 4 grid-strided float4 stores per thread ----
        int zb  = blockIdx.x - RUN_BLOCKS;
        int idx = zb * 256 + threadIdx.x;
        const float4 z4 = make_float4(0.f, 0.f, 0.f, 0.f);
        #pragma unroll
        for (int k = 0; k < 4; k++)
            out4[idx + k * ZERO_STRIDE] = z4;
        return;
    }

    // ---- ray-walk path ----
    int ray  = blockIdx.x * 256 + threadIdx.x;   // 0..16895
    int lane = threadIdx.x & 31;
    int wid  = ray >> 5;                         // 0..527
    int bn   = ray / RAYS_PER_BN;
    int hw   = ray - bn * RAYS_PER_BN;
    int h    = hw / FW;
    int w    = hw - h * FW;
    int b    = bn / NN;

    float iK[9], iPR[9], cmb[9];
    inv3(intrins + bn*9, iK);
    inv3(post_rots + bn*9, iPR);
    const float* R = rots + bn*9;
    #pragma unroll
    for (int r = 0; r < 3; r++)
        #pragma unroll
        for (int c = 0; c < 3; c++)
            cmb[r*3+c] = R[r*3+0]*iK[0*3+c] + R[r*3+1]*iK[1*3+c] + R[r*3+2]*iK[2*3+c];
    float t0 = trans[bn*3+0], t1 = trans[bn*3+1], t2 = trans[bn*3+2];
    float pt0 = post_trans[bn*3+0], pt1 = post_trans[bn*3+1], pt2 = post_trans[bn*3+2];

    float u = (float)w * (351.0f / 43.0f);
    float v = (float)h * (127.0f / 15.0f);
    float px  = u    - pt0;
    float py  = v    - pt1;
    float pz0 = 4.0f - pt2;

    float qx  = iPR[0]*px + iPR[1]*py + iPR[2]*pz0;
    float qy  = iPR[3]*px + iPR[4]*py + iPR[5]*pz0;
    float qz  = iPR[6]*px + iPR[7]*py + iPR[8]*pz0;
    float dqx = iPR[2], dqy = iPR[5], dqz = iPR[8];

    int2* region = g_runs + wid * RUNS_PER_WARP;
    unsigned lt_mask = (1u << lane) - 1u;

    int obase = b * (CC * SPATIAL);
    int cur = -1;
    int curStart = 0;
    int wcnt = 0;                  // warp-uniform running count

    #pragma unroll 1
    for (int d = 0; d < DD; d++) {
        float sx = qx * qz;
        float sy = qy * qz;
        float gx = cmb[0]*sx + cmb[1]*sy + cmb[2]*qz + t0;
        float gy = cmb[3]*sx + cmb[4]*sy + cmb[5]*qz + t1;
        float gz = cmb[6]*sx + cmb[7]*sy + cmb[8]*qz + t2;

        int ix = (int)((gx + 50.0f) / 0.5f);
        int iy = (int)((gy + 50.0f) / 0.5f);
        int iz = (int)((gz + 10.0f) / 20.0f);

        int o = -1;
        if (ix >= 0 && ix < NX && iy >= 0 && iy < NY && iz == 0)
            o = obase + ix * NY + iy;

        bool flush = (o != cur) && (cur >= 0);
        unsigned bal = __ballot_sync(0xffffffffu, flush);
        if (flush) {
            int p0 = (bn*DD + curStart) * RAYS_PER_BN + hw;
            region[wcnt + __popc(bal & lt_mask)] =
                make_int2(p0 | ((d - curStart) << 20), cur);
        }
        wcnt += __popc(bal);
        if (o != cur) { cur = o; curStart = d; }

        qx += dqx; qy += dqy; qz += dqz;
    }

    {   // final flush
        bool flush = (cur >= 0);
        unsigned bal = __ballot_sync(0xffffffffu, flush);
        if (flush) {
            int p0 = (bn*DD + curStart) * RAYS_PER_BN + hw;
            region[wcnt + __popc(bal & lt_mask)] =
                make_int2(p0 | ((DD - curStart) << 20), cur);
        }
        wcnt += __popc(bal);
    }
    if (lane == 0) g_warp_count[wid] = wcnt;
}

// ---------------- run scatter: prefetched recs + batched first loads ----------------
// Block s processes geometry-warp s's segment; warps take 8-run chunks.
// Records are loaded cooperatively (lanes 0..7) and shfl-broadcast; the 8
// first-depth float2 loads are issued back-to-back (MLP=8) before any
// accumulation. Consecutive same-offset runs merge in registers before the
// atomic flush. Lane l owns channels (2l, 2l+1).
#define CHUNK 8
__global__ void __launch_bounds__(256) scatter_runs_kernel(
        const float* __restrict__ x,
        float* __restrict__ out) {
    int seg  = blockIdx.x;
    int cnt  = g_warp_count[seg];
    const int2* runs = g_runs + seg * RUNS_PER_WARP;
    int wrp  = threadIdx.x >> 5;
    int lane = threadIdx.x & 31;
    const float2* xf2 = reinterpret_cast<const float2*>(x);

    for (int base = wrp * CHUNK; base < cnt; base += 8 * CHUNK) {
        int n = min(CHUNK, cnt - base);

        // cooperative record fetch: lanes 0..7 each load one rec, broadcast
        int2 myrec = make_int2(0, -1);
        if (lane < n) myrec = __ldg(runs + base + lane);
        int rx[CHUNK], ry[CHUNK];
        #pragma unroll
        for (int i = 0; i < CHUNK; i++) {
            rx[i] = __shfl_sync(0xffffffffu, myrec.x, i);
            ry[i] = __shfl_sync(0xffffffffu, myrec.y, i);
        }

        // phase 1: first-depth loads for all runs in the chunk (independent)
        float2 v[CHUNK];
        #pragma unroll
        for (int i = 0; i < CHUNK; i++) {
            if (i < n)
                v[i] = __ldg(xf2 + (size_t)(rx[i] & 0xFFFFF) * (CC/2) + lane);
        }

        // phase 2: tail depths (rare), merge by offset, flush
        int curOff = -1;
        float2 acc = make_float2(0.f, 0.f);
        #pragma unroll
        for (int i = 0; i < CHUNK; i++) {
            if (i >= n) break;
            int p0 = rx[i] & 0xFFFFF;
            int c  = rx[i] >> 20;
            float2 a = v[i];
            const float2* src = xf2 + (size_t)p0 * (CC/2) + lane;
            for (int j = 1; j < c; j++) {
                float2 vv = __ldg(src + (size_t)j * (RAYS_PER_BN * (CC/2)));
                a.x += vv.x; a.y += vv.y;
            }
            if (ry[i] != curOff) {
                if (curOff >= 0) {
                    float* dp = out + curOff + (size_t)(2*lane) * SPATIAL;
                    atomicAdd(dp,           acc.x);
                    atomicAdd(dp + SPATIAL, acc.y);
                }
                curOff = ry[i];
                acc = make_float2(0.f, 0.f);
            }
            acc.x += a.x; acc.y += a.y;
        }
        if (curOff >= 0) {
            float* dp = out + curOff + (size_t)(2*lane) * SPATIAL;
            atomicAdd(dp,           acc.x);
            atomicAdd(dp + SPATIAL, acc.y);
        }
    }
}

// ---------------- launch ----------------
extern "C" void kernel_launch(void* const* d_in, const int* in_sizes, int n_in,
                              void* d_out, int out_size) {
    const float* x          = (const float*)d_in[0];
    const float* rots       = (const float*)d_in[1];
    const float* trans      = (const float*)d_in[2];
    const float* intrins    = (const float*)d_in[3];
    const float* post_rots  = (const float*)d_in[4];
    const float* post_trans = (const float*)d_in[5];
    float* out = (float*)d_out;

    // fused: 66 ray-walk blocks + 2500 zero blocks
    run_zero_kernel<<<RUN_BLOCKS + ZERO_BLOCKS, 256>>>(
        rots, intrins, post_rots, trans, post_trans, (float4*)out);

    // one block per geometry-warp segment
    scatter_runs_kernel<<<NWARPS, 256>>>(x, out);
}

// round 9
// speedup vs baseline: 3.4472x; 1.1260x over previous
#include <cuda_runtime.h>
#include <cstdint>

// ---------------- problem constants ----------------
#define BB 4
#define NN 6
#define DD 41
#define FH 16
#define FW 44
#define CC 64
#define NX 200
#define NY 200
#define NP (BB*NN*DD*FH*FW)        // 692736
#define RAYS_PER_BN (FH*FW)        // 704
#define NRAYS (BB*NN*RAYS_PER_BN)  // 16896
#define NWARPS (NRAYS/32)          // 528 geometry warps
#define RUNS_PER_WARP (32*DD)      // 1312 ; 528*1312 == NP exactly
#define SPATIAL (NX*NY)            // 40000

#define RUN_BLOCKS  (NRAYS/256)    // 66
#define ZERO_BLOCKS 2500           // 2500*256*4 float4 = 2,560,000 exactly
#define ZERO_STRIDE (ZERO_BLOCKS*256)

#define MAXRUN 4                   // max depths per emitted run record
#define CHUNK 8
#define BLKS_PER_SEG 4

// run records, one private region per geometry warp:
// rec.x = p_start | (count<<20), rec.y = output offset (floats)
__device__ int2 g_runs[NP];
__device__ int  g_warp_count[NWARPS];

// ---------------- 3x3 inverse (adjugate) ----------------
__device__ __forceinline__ void inv3(const float* m, float* o) {
    float a=m[0],b=m[1],c=m[2],d=m[3],e=m[4],f=m[5],g=m[6],h=m[7],i=m[8];
    float A  =  (e*i - f*h);
    float Bm = -(d*i - f*g);
    float Cm =  (d*h - e*g);
    float det = a*A + b*Bm + c*Cm;
    float inv = 1.0f / det;
    o[0] =  A*inv;
    o[1] = -(b*i - c*h)*inv;
    o[2] =  (b*f - c*e)*inv;
    o[3] =  Bm*inv;
    o[4] =  (a*i - c*g)*inv;
    o[5] = -(a*f - c*d)*inv;
    o[6] =  Cm*inv;
    o[7] = -(a*h - b*g)*inv;
    o[8] =  (a*e - b*d)*inv;
}

// ---------------- fused: ray walk (blocks 0..65) + output zero (rest) ----------------
__global__ void __launch_bounds__(256) run_zero_kernel(
        const float* __restrict__ rots,
        const float* __restrict__ intrins,
        const float* __restrict__ post_rots,
        const float* __restrict__ trans,
        const float* __restrict__ post_trans,
        float4* __restrict__ out4) {
    if (blockIdx.x >= RUN_BLOCKS) {
        int zb  = blockIdx.x - RUN_BLOCKS;
        int idx = zb * 256 + threadIdx.x;
        const float4 z4 = make_float4(0.f, 0.f, 0.f, 0.f);
        #pragma unroll
        for (int k = 0; k < 4; k++)
            out4[idx + k * ZERO_STRIDE] = z4;
        return;
    }

    // ---- ray-walk path ----
    int ray  = blockIdx.x * 256 + threadIdx.x;   // 0..16895
    int lane = threadIdx.x & 31;
    int wid  = ray >> 5;                         // 0..527
    int bn   = ray / RAYS_PER_BN;
    int hw   = ray - bn * RAYS_PER_BN;
    int h    = hw / FW;
    int w    = hw - h * FW;
    int b    = bn / NN;

    float iK[9], iPR[9], cmb[9];
    inv3(intrins + bn*9, iK);
    inv3(post_rots + bn*9, iPR);
    const float* R = rots + bn*9;
    #pragma unroll
    for (int r = 0; r < 3; r++)
        #pragma unroll
        for (int c = 0; c < 3; c++)
            cmb[r*3+c] = R[r*3+0]*iK[0*3+c] + R[r*3+1]*iK[1*3+c] + R[r*3+2]*iK[2*3+c];
    float t0 = trans[bn*3+0], t1 = trans[bn*3+1], t2 = trans[bn*3+2];
    float pt0 = post_trans[bn*3+0], pt1 = post_trans[bn*3+1], pt2 = post_trans[bn*3+2];

    float u = (float)w * (351.0f / 43.0f);
    float v = (float)h * (127.0f / 15.0f);
    float px  = u    - pt0;
    float py  = v    - pt1;
    float pz0 = 4.0f - pt2;

    float qx  = iPR[0]*px + iPR[1]*py + iPR[2]*pz0;
    float qy  = iPR[3]*px + iPR[4]*py + iPR[5]*pz0;
    float qz  = iPR[6]*px + iPR[7]*py + iPR[8]*pz0;
    float dqx = iPR[2], dqy = iPR[5], dqz = iPR[8];

    int2* region = g_runs + wid * RUNS_PER_WARP;
    unsigned lt_mask = (1u << lane) - 1u;

    int obase = b * (CC * SPATIAL);
    int cur = -1;
    int curStart = 0;
    int wcnt = 0;                  // warp-uniform running count

    #pragma unroll 1
    for (int d = 0; d < DD; d++) {
        float sx = qx * qz;
        float sy = qy * qz;
        float gx = cmb[0]*sx + cmb[1]*sy + cmb[2]*qz + t0;
        float gy = cmb[3]*sx + cmb[4]*sy + cmb[5]*qz + t1;
        float gz = cmb[6]*sx + cmb[7]*sy + cmb[8]*qz + t2;

        int ix = (int)((gx + 50.0f) / 0.5f);
        int iy = (int)((gy + 50.0f) / 0.5f);
        int iz = (int)((gz + 10.0f) / 20.0f);

        int o = -1;
        if (ix >= 0 && ix < NX && iy >= 0 && iy < NY && iz == 0)
            o = obase + ix * NY + iy;

        // flush on voxel change OR when run reaches MAXRUN depths
        bool newvox = (o != cur);
        bool flush  = (cur >= 0) && (newvox || (d - curStart) == MAXRUN);
        unsigned bal = __ballot_sync(0xffffffffu, flush);
        if (flush) {
            int p0 = (bn*DD + curStart) * RAYS_PER_BN + hw;
            region[wcnt + __popc(bal & lt_mask)] =
                make_int2(p0 | ((d - curStart) << 20), cur);
        }
        wcnt += __popc(bal);
        if (flush && !newvox) curStart = d;     // split long run, same voxel
        if (newvox) { cur = o; curStart = d; }

        qx += dqx; qy += dqy; qz += dqz;
    }

    {   // final flush (length <= MAXRUN guaranteed by splitting)
        bool flush = (cur >= 0);
        unsigned bal = __ballot_sync(0xffffffffu, flush);
        if (flush) {
            int p0 = (bn*DD + curStart) * RAYS_PER_BN + hw;
            region[wcnt + __popc(bal & lt_mask)] =
                make_int2(p0 | ((DD - curStart) << 20), cur);
        }
        wcnt += __popc(bal);
    }
    if (lane == 0) g_warp_count[wid] = wcnt;
}

// ---------------- run scatter: depth-major batched loads ----------------
// BLKS_PER_SEG blocks per segment; 32 warps serve each segment, each taking
// 8-run chunks. Records fetched cooperatively (lanes 0..7) and broadcast.
// Loads proceed depth-major: per level j, all 8 runs' predicated float2 loads
// issue back-to-back (MLP=8), then accumulate. Max chain = 4 levels.
// Consecutive same-offset runs merge in registers before the atomic flush.
// Lane l owns channels (2l, 2l+1).
__global__ void __launch_bounds__(256) scatter_runs_kernel(
        const float* __restrict__ x,
        float* __restrict__ out) {
    int seg  = blockIdx.x / BLKS_PER_SEG;
    int sub  = blockIdx.x - seg * BLKS_PER_SEG;
    int cnt  = g_warp_count[seg];
    const int2* runs = g_runs + seg * RUNS_PER_WARP;
    int wrp  = threadIdx.x >> 5;
    int lane = threadIdx.x & 31;
    int gw   = sub * 8 + wrp;          // 0..31 warps serving this segment
    const float2* xf2 = reinterpret_cast<const float2*>(x);

    for (int base = gw * CHUNK; base < cnt; base += 32 * CHUNK) {
        int n = min(CHUNK, cnt - base);

        // cooperative record fetch: lanes 0..7 each load one rec, broadcast
        int2 myrec = make_int2(0, -1);
        if (lane < n) myrec = __ldg(runs + base + lane);
        int rx[CHUNK], ry[CHUNK];
        #pragma unroll
        for (int i = 0; i < CHUNK; i++) {
            rx[i] = __shfl_sync(0xffffffffu, myrec.x, i);
            ry[i] = __shfl_sync(0xffffffffu, myrec.y, i);
        }

        // depth-major accumulation: level j loads for all runs are independent
        float2 acc[CHUNK];
        #pragma unroll
        for (int i = 0; i < CHUNK; i++) acc[i] = make_float2(0.f, 0.f);

        #pragma unroll
        for (int j = 0; j < MAXRUN; j++) {
            float2 v[CHUNK];
            #pragma unroll
            for (int i = 0; i < CHUNK; i++) {
                int c = rx[i] >> 20;
                if (i < n && j < c) {
                    int p = (rx[i] & 0xFFFFF) + j * RAYS_PER_BN;
                    v[i] = __ldg(xf2 + (size_t)p * (CC/2) + lane);
                }
            }
            #pragma unroll
            for (int i = 0; i < CHUNK; i++) {
                int c = rx[i] >> 20;
                if (i < n && j < c) { acc[i].x += v[i].x; acc[i].y += v[i].y; }
            }
        }

        // merge consecutive same-offset runs, then flush
        int curOff = -1;
        float2 a = make_float2(0.f, 0.f);
        #pragma unroll
        for (int i = 0; i < CHUNK; i++) {
            if (i >= n) break;
            if (ry[i] != curOff) {
                if (curOff >= 0) {
                    float* dp = out + curOff + (size_t)(2*lane) * SPATIAL;
                    atomicAdd(dp,           a.x);
                    atomicAdd(dp + SPATIAL, a.y);
                }
                curOff = ry[i];
                a = make_float2(0.f, 0.f);
            }
            a.x += acc[i].x; a.y += acc[i].y;
        }
        if (curOff >= 0) {
            float* dp = out + curOff + (size_t)(2*lane) * SPATIAL;
            atomicAdd(dp,           a.x);
            atomicAdd(dp + SPATIAL, a.y);
        }
    }
}

// ---------------- launch ----------------
extern "C" void kernel_launch(void* const* d_in, const int* in_sizes, int n_in,
                              void* d_out, int out_size) {
    const float* x          = (const float*)d_in[0];
    const float* rots       = (const float*)d_in[1];
    const float* trans      = (const float*)d_in[2];
    const float* intrins    = (const float*)d_in[3];
    const float* post_rots  = (const float*)d_in[4];
    const float* post_trans = (const float*)d_in[5];
    float* out = (float*)d_out;

    // fused: 66 ray-walk blocks + 2500 zero blocks
    run_zero_kernel<<<RUN_BLOCKS + ZERO_BLOCKS, 256>>>(
        rots, intrins, post_rots, trans, post_trans, (float4*)out);

    // 4 blocks per geometry-warp segment
    scatter_runs_kernel<<<NWARPS * BLKS_PER_SEG, 256>>>(x, out);
}

// round 10
// speedup vs baseline: 3.5260x; 1.0229x over previous
#include <cuda_runtime.h>
#include <cstdint>

// ---------------- problem constants ----------------
#define BB 4
#define NN 6
#define DD 41
#define FH 16
#define FW 44
#define CC 64
#define NX 200
#define NY 200
#define NP (BB*NN*DD*FH*FW)        // 692736
#define RAYS_PER_BN (FH*FW)        // 704
#define NRAYS (BB*NN*RAYS_PER_BN)  // 16896
#define NWARPS (NRAYS/32)          // 528 geometry warps
#define RUNS_PER_WARP (32*DD)      // 1312 ; 528*1312 == NP exactly
#define SPATIAL (NX*NY)            // 40000
#define WORDS_PER_B (SPATIAL/32)   // 1250 bitmap words per batch

#define RUN_BLOCKS (NRAYS/256)     // 66
#define MAXRUN 4                   // max depths per emitted run record
#define CHUNK 8
#define BLKS_PER_SEG 4

// channel-last scratch accumulator: (B, NX*NY, C).
// INVARIANT: zero at entry (load-time zero init; out_write re-zeroes touched rows).
__device__ __align__(16) float g_scratch[BB * SPATIAL * CC];
// touched-voxel bitmap, 1 bit per (b, s). INVARIANT: zero at entry.
__device__ unsigned g_bitmap[BB * WORDS_PER_B];
// run records: rec.x = p_start | (count<<20), rec.y = voxel index b*SPATIAL+s
__device__ int2 g_runs[NP];
__device__ int  g_warp_count[NWARPS];

// ---------------- 3x3 inverse (adjugate) ----------------
__device__ __forceinline__ void inv3(const float* m, float* o) {
    float a=m[0],b=m[1],c=m[2],d=m[3],e=m[4],f=m[5],g=m[6],h=m[7],i=m[8];
    float A  =  (e*i - f*h);
    float Bm = -(d*i - f*g);
    float Cm =  (d*h - e*g);
    float det = a*A + b*Bm + c*Cm;
    float inv = 1.0f / det;
    o[0] =  A*inv;
    o[1] = -(b*i - c*h)*inv;
    o[2] =  (b*f - c*e)*inv;
    o[3] =  Bm*inv;
    o[4] =  (a*i - c*g)*inv;
    o[5] = -(a*f - c*d)*inv;
    o[6] =  Cm*inv;
    o[7] = -(a*h - b*g)*inv;
    o[8] =  (a*e - b*d)*inv;
}

// ---------------- per-ray walk -> runs + touched bitmap ----------------
__global__ void __launch_bounds__(256) run_kernel(
        const float* __restrict__ rots,
        const float* __restrict__ intrins,
        const float* __restrict__ post_rots,
        const float* __restrict__ trans,
        const float* __restrict__ post_trans) {
    int ray  = blockIdx.x * 256 + threadIdx.x;   // 0..16895
    int lane = threadIdx.x & 31;
    int wid  = ray >> 5;                         // 0..527
    int bn   = ray / RAYS_PER_BN;
    int hw   = ray - bn * RAYS_PER_BN;
    int h    = hw / FW;
    int w    = hw - h * FW;
    int b    = bn / NN;

    float iK[9], iPR[9], cmb[9];
    inv3(intrins + bn*9, iK);
    inv3(post_rots + bn*9, iPR);
    const float* R = rots + bn*9;
    #pragma unroll
    for (int r = 0; r < 3; r++)
        #pragma unroll
        for (int c = 0; c < 3; c++)
            cmb[r*3+c] = R[r*3+0]*iK[0*3+c] + R[r*3+1]*iK[1*3+c] + R[r*3+2]*iK[2*3+c];
    float t0 = trans[bn*3+0], t1 = trans[bn*3+1], t2 = trans[bn*3+2];
    float pt0 = post_trans[bn*3+0], pt1 = post_trans[bn*3+1], pt2 = post_trans[bn*3+2];

    float u = (float)w * (351.0f / 43.0f);
    float v = (float)h * (127.0f / 15.0f);
    float px  = u    - pt0;
    float py  = v    - pt1;
    float pz0 = 4.0f - pt2;

    float qx  = iPR[0]*px + iPR[1]*py + iPR[2]*pz0;
    float qy  = iPR[3]*px + iPR[4]*py + iPR[5]*pz0;
    float qz  = iPR[6]*px + iPR[7]*py + iPR[8]*pz0;
    float dqx = iPR[2], dqy = iPR[5], dqz = iPR[8];

    int2* region = g_runs + wid * RUNS_PER_WARP;
    unsigned lt_mask = (1u << lane) - 1u;

    int obase = b * SPATIAL;
    int cur = -1;
    int curStart = 0;
    int wcnt = 0;                  // warp-uniform running count

    #pragma unroll 1
    for (int d = 0; d < DD; d++) {
        float sx = qx * qz;
        float sy = qy * qz;
        float gx = cmb[0]*sx + cmb[1]*sy + cmb[2]*qz + t0;
        float gy = cmb[3]*sx + cmb[4]*sy + cmb[5]*qz + t1;
        float gz = cmb[6]*sx + cmb[7]*sy + cmb[8]*qz + t2;

        int ix = (int)((gx + 50.0f) / 0.5f);
        int iy = (int)((gy + 50.0f) / 0.5f);
        int iz = (int)((gz + 10.0f) / 20.0f);

        int o = -1;
        if (ix >= 0 && ix < NX && iy >= 0 && iy < NY && iz == 0)
            o = obase + ix * NY + iy;          // voxel index

        bool newvox = (o != cur);
        // mark touched voxel (fire-and-forget OR)
        if (newvox && o >= 0)
            atomicOr(&g_bitmap[o >> 5], 1u << (o & 31));

        bool flush = (cur >= 0) && (newvox || (d - curStart) == MAXRUN);
        unsigned bal = __ballot_sync(0xffffffffu, flush);
        if (flush) {
            int p0 = (bn*DD + curStart) * RAYS_PER_BN + hw;
            region[wcnt + __popc(bal & lt_mask)] =
                make_int2(p0 | ((d - curStart) << 20), cur);
        }
        wcnt += __popc(bal);
        if (flush && !newvox) curStart = d;     // split long run, same voxel
        if (newvox) { cur = o; curStart = d; }

        qx += dqx; qy += dqy; qz += dqz;
    }

    {   // final flush
        bool flush = (cur >= 0);
        unsigned bal = __ballot_sync(0xffffffffu, flush);
        if (flush) {
            int p0 = (bn*DD + curStart) * RAYS_PER_BN + hw;
            region[wcnt + __popc(bal & lt_mask)] =
                make_int2(p0 | ((DD - curStart) << 20), cur);
        }
        wcnt += __popc(bal);
    }
    if (lane == 0) g_warp_count[wid] = wcnt;
}

// ---------------- run scatter: depth-major loads, coalesced red.v2 flush ----------------
// Lane l owns channels (2l, 2l+1) — contiguous in the channel-last scratch,
// so each flush is 32 x red.global.add.v2.f32 covering 256 contiguous bytes.
__global__ void __launch_bounds__(256) scatter_runs_kernel(
        const float* __restrict__ x) {
    int seg  = blockIdx.x / BLKS_PER_SEG;
    int sub  = blockIdx.x - seg * BLKS_PER_SEG;
    int cnt  = g_warp_count[seg];
    const int2* runs = g_runs + seg * RUNS_PER_WARP;
    int wrp  = threadIdx.x >> 5;
    int lane = threadIdx.x & 31;
    int gw   = sub * 8 + wrp;          // 0..31 warps serving this segment
    const float2* xf2 = reinterpret_cast<const float2*>(x);

    for (int base = gw * CHUNK; base < cnt; base += 32 * CHUNK) {
        int n = min(CHUNK, cnt - base);

        // cooperative record fetch: lanes 0..7 each load one rec, broadcast
        int2 myrec = make_int2(0, -1);
        if (lane < n) myrec = __ldg(runs + base + lane);
        int rx[CHUNK], ry[CHUNK];
        #pragma unroll
        for (int i = 0; i < CHUNK; i++) {
            rx[i] = __shfl_sync(0xffffffffu, myrec.x, i);
            ry[i] = __shfl_sync(0xffffffffu, myrec.y, i);
        }

        // depth-major accumulation: level-j loads for all runs are independent
        float2 acc[CHUNK];
        #pragma unroll
        for (int i = 0; i < CHUNK; i++) acc[i] = make_float2(0.f, 0.f);

        #pragma unroll
        for (int j = 0; j < MAXRUN; j++) {
            float2 v[CHUNK];
            #pragma unroll
            for (int i = 0; i < CHUNK; i++) {
                int c = rx[i] >> 20;
                if (i < n && j < c) {
                    int p = (rx[i] & 0xFFFFF) + j * RAYS_PER_BN;
                    v[i] = __ldg(xf2 + (size_t)p * (CC/2) + lane);
                }
            }
            #pragma unroll
            for (int i = 0; i < CHUNK; i++) {
                int c = rx[i] >> 20;
                if (i < n && j < c) { acc[i].x += v[i].x; acc[i].y += v[i].y; }
            }
        }

        // merge consecutive same-voxel runs, then coalesced vector-red flush
        int curOff = -1;
        float2 a = make_float2(0.f, 0.f);
        #pragma unroll
        for (int i = 0; i < CHUNK; i++) {
            if (i >= n) break;
            if (ry[i] != curOff) {
                if (curOff >= 0) {
                    float* dp = g_scratch + (size_t)curOff * CC + 2*lane;
                    asm volatile("red.global.add.v2.f32 [%0], {%1, %2};"
                                 :: "l"(dp), "f"(a.x), "f"(a.y) : "memory");
                }
                curOff = ry[i];
                a = make_float2(0.f, 0.f);
            }
            a.x += acc[i].x; a.y += acc[i].y;
        }
        if (curOff >= 0) {
            float* dp = g_scratch + (size_t)curOff * CC + 2*lane;
            asm volatile("red.global.add.v2.f32 [%0], {%1, %2};"
                         :: "l"(dp), "f"(a.x), "f"(a.y) : "memory");
        }
    }
}

// ---------------- output write: zeros + touched-voxel gather + cleanup ----------------
// Block = one batch b, one 32-voxel tile (all 64 channels). Warp w handles
// channels [8w, 8w+8) for 32 consecutive voxels. After writing out, the block
// re-zeroes its touched scratch rows and clears its bitmap word (exclusive
// ownership -> race-free), restoring the zero-invariants for the next launch.
__global__ void __launch_bounds__(256) out_write_kernel(float* __restrict__ out) {
    __shared__ unsigned sw;
    int b    = blockIdx.y;
    int tile = blockIdx.x;              // 0..1249
    int tid  = threadIdx.x;
    int lane = tid & 31;
    int wrp  = tid >> 5;                // 0..7

    if (tid == 0) sw = g_bitmap[b * WORDS_PER_B + tile];
    __syncthreads();
    unsigned word = sw;

    int s0 = tile * 32;
    float* sc = g_scratch + ((size_t)b * SPATIAL + s0) * CC;

    float vals[8];
    if ((word >> lane) & 1u) {
        const float4* p = reinterpret_cast<const float4*>(sc + lane*CC + wrp*8);
        float4 v0 = p[0];
        float4 v1 = p[1];
        vals[0]=v0.x; vals[1]=v0.y; vals[2]=v0.z; vals[3]=v0.w;
        vals[4]=v1.x; vals[5]=v1.y; vals[6]=v1.z; vals[7]=v1.w;
    } else {
        #pragma unroll
        for (int k = 0; k < 8; k++) vals[k] = 0.f;
    }

    float* op = out + ((size_t)b * CC + wrp*8) * SPATIAL + s0 + lane;
    #pragma unroll
    for (int k = 0; k < 8; k++)
        op[(size_t)k * SPATIAL] = vals[k];

    if (word == 0) return;
    __syncthreads();

    // re-zero touched scratch rows: thread t -> voxel t>>3, floats [(t&7)*8, +8)
    int vox = tid >> 3;
    if ((word >> vox) & 1u) {
        float4* p = reinterpret_cast<float4*>(sc + vox*CC + (tid & 7)*8);
        const float4 z4 = make_float4(0.f, 0.f, 0.f, 0.f);
        p[0] = z4;
        p[1] = z4;
    }
    if (tid == 0) g_bitmap[b * WORDS_PER_B + tile] = 0u;
}

// ---------------- launch ----------------
extern "C" void kernel_launch(void* const* d_in, const int* in_sizes, int n_in,
                              void* d_out, int out_size) {
    const float* x          = (const float*)d_in[0];
    const float* rots       = (const float*)d_in[1];
    const float* trans      = (const float*)d_in[2];
    const float* intrins    = (const float*)d_in[3];
    const float* post_rots  = (const float*)d_in[4];
    const float* post_trans = (const float*)d_in[5];
    float* out = (float*)d_out;

    // 1. ray walk -> run list + touched bitmap
    run_kernel<<<RUN_BLOCKS, 256>>>(rots, intrins, post_rots, trans, post_trans);

    // 2. feature accumulate into channel-last scratch (coalesced vector reds)
    scatter_runs_kernel<<<NWARPS * BLKS_PER_SEG, 256>>>(x);

    // 3. write output (zeros + gather), restore scratch/bitmap invariants
    out_write_kernel<<<dim3(WORDS_PER_B, BB), 256>>>(out);
}

// round 11
// speedup vs baseline: 3.9906x; 1.1318x over previous
#include <cuda_runtime.h>
#include <cstdint>

// ---------------- problem constants ----------------
#define BB 4
#define NN 6
#define DD 41
#define FH 16
#define FW 44
#define CC 64
#define NX 200
#define NY 200
#define NP (BB*NN*DD*FH*FW)        // 692736
#define RAYS_PER_BN (FH*FW)        // 704
#define NRAYS (BB*NN*RAYS_PER_BN)  // 16896
#define SPATIAL (NX*NY)            // 40000
#define WORDS_PER_B (SPATIAL/32)   // 1250 bitmap words per batch

// depth split: 4 chunks of <=11 depths
#define NCHUNK 4
#define DCHUNK 11                  // chunk c covers [c*11, min(41, c*11+11))
#define NWARPS2 (NRAYS*NCHUNK/32)  // 2112 emission warps
#define RUNS_PER_WARP2 (32*DCHUNK) // 352 slots per warp region

#define RUN_BLOCKS (NRAYS*NCHUNK/256)  // 264
#define MAXRUN 4                   // max depths per emitted run record
#define CHUNK 8
#define BLKS_PER_SEG 2

// channel-last scratch accumulator: (B, NX*NY, C).
// INVARIANT: zero at entry (load-time zero init; out_write re-zeroes touched rows).
__device__ __align__(16) float g_scratch[BB * SPATIAL * CC];
// touched-voxel bitmap, 1 bit per (b, s). INVARIANT: zero at entry.
__device__ unsigned g_bitmap[BB * WORDS_PER_B];
// run records: rec.x = p_start | (count<<20), rec.y = voxel index b*SPATIAL+s
__device__ int2 g_runs[NWARPS2 * RUNS_PER_WARP2];
__device__ int  g_warp_count[NWARPS2];

// ---------------- 3x3 inverse (adjugate) ----------------
__device__ __forceinline__ void inv3(const float* m, float* o) {
    float a=m[0],b=m[1],c=m[2],d=m[3],e=m[4],f=m[5],g=m[6],h=m[7],i=m[8];
    float A  =  (e*i - f*h);
    float Bm = -(d*i - f*g);
    float Cm =  (d*h - e*g);
    float det = a*A + b*Bm + c*Cm;
    float inv = 1.0f / det;
    o[0] =  A*inv;
    o[1] = -(b*i - c*h)*inv;
    o[2] =  (b*f - c*e)*inv;
    o[3] =  Bm*inv;
    o[4] =  (a*i - c*g)*inv;
    o[5] = -(a*f - c*d)*inv;
    o[6] =  Cm*inv;
    o[7] = -(a*h - b*g)*inv;
    o[8] =  (a*e - b*d)*inv;
}

// ---------------- per-(ray, depth-chunk) walk -> runs + touched bitmap ----------------
// thread t: chunk = t / NRAYS, ray = t % NRAYS. Each thread walks <=11 depths.
__global__ void __launch_bounds__(256) run_kernel(
        const float* __restrict__ rots,
        const float* __restrict__ intrins,
        const float* __restrict__ post_rots,
        const float* __restrict__ trans,
        const float* __restrict__ post_trans) {
    int t    = blockIdx.x * 256 + threadIdx.x;
    int lane = threadIdx.x & 31;
    int wid  = t >> 5;                           // 0..2111
    int chnk = t / NRAYS;                        // 0..3
    int ray  = t - chnk * NRAYS;                 // 0..16895
    int bn   = ray / RAYS_PER_BN;
    int hw   = ray - bn * RAYS_PER_BN;
    int h    = hw / FW;
    int w    = hw - h * FW;
    int b    = bn / NN;

    int d0 = chnk * DCHUNK;
    int d1 = min(DD, d0 + DCHUNK);

    float iK[9], iPR[9], cmb[9];
    inv3(intrins + bn*9, iK);
    inv3(post_rots + bn*9, iPR);
    const float* R = rots + bn*9;
    #pragma unroll
    for (int r = 0; r < 3; r++)
        #pragma unroll
        for (int c = 0; c < 3; c++)
            cmb[r*3+c] = R[r*3+0]*iK[0*3+c] + R[r*3+1]*iK[1*3+c] + R[r*3+2]*iK[2*3+c];
    float t0 = trans[bn*3+0], t1 = trans[bn*3+1], t2 = trans[bn*3+2];
    float pt0 = post_trans[bn*3+0], pt1 = post_trans[bn*3+1], pt2 = post_trans[bn*3+2];

    float u = (float)w * (351.0f / 43.0f);
    float v = (float)h * (127.0f / 15.0f);
    float px  = u - pt0;
    float py  = v - pt1;
    float pz0 = (4.0f + (float)d0) - pt2;

    float qx  = iPR[0]*px + iPR[1]*py + iPR[2]*pz0;
    float qy  = iPR[3]*px + iPR[4]*py + iPR[5]*pz0;
    float qz  = iPR[6]*px + iPR[7]*py + iPR[8]*pz0;
    float dqx = iPR[2], dqy = iPR[5], dqz = iPR[8];

    int2* region = g_runs + wid * RUNS_PER_WARP2;
    unsigned lt_mask = (1u << lane) - 1u;

    int obase = b * SPATIAL;
    int cur = -1;
    int curStart = d0;
    int wcnt = 0;                  // warp-uniform running count

    #pragma unroll 1
    for (int d = d0; d < d1; d++) {
        float sx = qx * qz;
        float sy = qy * qz;
        float gx = cmb[0]*sx + cmb[1]*sy + cmb[2]*qz + t0;
        float gy = cmb[3]*sx + cmb[4]*sy + cmb[5]*qz + t1;
        float gz = cmb[6]*sx + cmb[7]*sy + cmb[8]*qz + t2;

        int ix = (int)((gx + 50.0f) / 0.5f);
        int iy = (int)((gy + 50.0f) / 0.5f);
        int iz = (int)((gz + 10.0f) / 20.0f);

        int o = -1;
        if (ix >= 0 && ix < NX && iy >= 0 && iy < NY && iz == 0)
            o = obase + ix * NY + iy;          // voxel index

        bool newvox = (o != cur);
        if (newvox && o >= 0)
            atomicOr(&g_bitmap[o >> 5], 1u << (o & 31));

        bool flush = (cur >= 0) && (newvox || (d - curStart) == MAXRUN);
        unsigned bal = __ballot_sync(0xffffffffu, flush);
        if (flush) {
            int p0 = (bn*DD + curStart) * RAYS_PER_BN + hw;
            region[wcnt + __popc(bal & lt_mask)] =
                make_int2(p0 | ((d - curStart) << 20), cur);
        }
        wcnt += __popc(bal);
        if (flush && !newvox) curStart = d;     // split long run, same voxel
        if (newvox) { cur = o; curStart = d; }

        qx += dqx; qy += dqy; qz += dqz;
    }

    {   // final flush
        bool flush = (cur >= 0);
        unsigned bal = __ballot_sync(0xffffffffu, flush);
        if (flush) {
            int p0 = (bn*DD + curStart) * RAYS_PER_BN + hw;
            region[wcnt + __popc(bal & lt_mask)] =
                make_int2(p0 | ((d1 - curStart) << 20), cur);
        }
        wcnt += __popc(bal);
    }
    if (lane == 0) g_warp_count[wid] = wcnt;
}

// ---------------- run scatter: depth-major loads, coalesced red.v2 flush ----------------
// Lane l owns channels (2l, 2l+1) — contiguous in the channel-last scratch,
// so each flush is 32 x red.global.add.v2.f32 covering 256 contiguous bytes.
__global__ void __launch_bounds__(256) scatter_runs_kernel(
        const float* __restrict__ x) {
    int seg  = blockIdx.x / BLKS_PER_SEG;
    int sub  = blockIdx.x - seg * BLKS_PER_SEG;
    int cnt  = g_warp_count[seg];
    if (cnt == 0) return;
    const int2* runs = g_runs + seg * RUNS_PER_WARP2;
    int wrp  = threadIdx.x >> 5;
    int lane = threadIdx.x & 31;
    int gw   = sub * 8 + wrp;          // 0..15 warps serving this segment
    const float2* xf2 = reinterpret_cast<const float2*>(x);

    for (int base = gw * CHUNK; base < cnt; base += BLKS_PER_SEG * 8 * CHUNK) {
        int n = min(CHUNK, cnt - base);

        // cooperative record fetch: lanes 0..7 each load one rec, broadcast
        int2 myrec = make_int2(0, -1);
        if (lane < n) myrec = __ldg(runs + base + lane);
        int rx[CHUNK], ry[CHUNK];
        #pragma unroll
        for (int i = 0; i < CHUNK; i++) {
            rx[i] = __shfl_sync(0xffffffffu, myrec.x, i);
            ry[i] = __shfl_sync(0xffffffffu, myrec.y, i);
        }

        // depth-major accumulation: level-j loads for all runs are independent
        float2 acc[CHUNK];
        #pragma unroll
        for (int i = 0; i < CHUNK; i++) acc[i] = make_float2(0.f, 0.f);

        #pragma unroll
        for (int j = 0; j < MAXRUN; j++) {
            float2 v[CHUNK];
            #pragma unroll
            for (int i = 0; i < CHUNK; i++) {
                int c = rx[i] >> 20;
                if (i < n && j < c) {
                    int p = (rx[i] & 0xFFFFF) + j * RAYS_PER_BN;
                    v[i] = __ldg(xf2 + (size_t)p * (CC/2) + lane);
                }
            }
            #pragma unroll
            for (int i = 0; i < CHUNK; i++) {
                int c = rx[i] >> 20;
                if (i < n && j < c) { acc[i].x += v[i].x; acc[i].y += v[i].y; }
            }
        }

        // merge consecutive same-voxel runs, then coalesced vector-red flush
        int curOff = -1;
        float2 a = make_float2(0.f, 0.f);
        #pragma unroll
        for (int i = 0; i < CHUNK; i++) {
            if (i >= n) break;
            if (ry[i] != curOff) {
                if (curOff >= 0) {
                    float* dp = g_scratch + (size_t)curOff * CC + 2*lane;
                    asm volatile("red.global.add.v2.f32 [%0], {%1, %2};"
                                 :: "l"(dp), "f"(a.x), "f"(a.y) : "memory");
                }
                curOff = ry[i];
                a = make_float2(0.f, 0.f);
            }
            a.x += acc[i].x; a.y += acc[i].y;
        }
        if (curOff >= 0) {
            float* dp = g_scratch + (size_t)curOff * CC + 2*lane;
            asm volatile("red.global.add.v2.f32 [%0], {%1, %2};"
                         :: "l"(dp), "f"(a.x), "f"(a.y) : "memory");
        }
    }
}

// ---------------- output write: zeros + touched-voxel gather + cleanup ----------------
__global__ void __launch_bounds__(256) out_write_kernel(float* __restrict__ out) {
    __shared__ unsigned sw;
    int b    = blockIdx.y;
    int tile = blockIdx.x;              // 0..1249
    int tid  = threadIdx.x;
    int lane = tid & 31;
    int wrp  = tid >> 5;                // 0..7

    if (tid == 0) sw = g_bitmap[b * WORDS_PER_B + tile];
    __syncthreads();
    unsigned word = sw;

    int s0 = tile * 32;
    float* sc = g_scratch + ((size_t)b * SPATIAL + s0) * CC;

    float vals[8];
    if ((word >> lane) & 1u) {
        const float4* p = reinterpret_cast<const float4*>(sc + lane*CC + wrp*8);
        float4 v0 = p[0];
        float4 v1 = p[1];
        vals[0]=v0.x; vals[1]=v0.y; vals[2]=v0.z; vals[3]=v0.w;
        vals[4]=v1.x; vals[5]=v1.y; vals[6]=v1.z; vals[7]=v1.w;
    } else {
        #pragma unroll
        for (int k = 0; k < 8; k++) vals[k] = 0.f;
    }

    float* op = out + ((size_t)b * CC + wrp*8) * SPATIAL + s0 + lane;
    #pragma unroll
    for (int k = 0; k < 8; k++)
        op[(size_t)k * SPATIAL] = vals[k];

    if (word == 0) return;
    __syncthreads();

    // re-zero touched scratch rows: thread t -> voxel t>>3, floats [(t&7)*8, +8)
    int vox = tid >> 3;
    if ((word >> vox) & 1u) {
        float4* p = reinterpret_cast<float4*>(sc + vox*CC + (tid & 7)*8);
        const float4 z4 = make_float4(0.f, 0.f, 0.f, 0.f);
        p[0] = z4;
        p[1] = z4;
    }
    if (tid == 0) g_bitmap[b * WORDS_PER_B + tile] = 0u;
}

// ---------------- launch ----------------
extern "C" void kernel_launch(void* const* d_in, const int* in_sizes, int n_in,
                              void* d_out, int out_size) {
    const float* x          = (const float*)d_in[0];
    const float* rots       = (const float*)d_in[1];
    const float* trans      = (const float*)d_in[2];
    const float* intrins    = (const float*)d_in[3];
    const float* post_rots  = (const float*)d_in[4];
    const float* post_trans = (const float*)d_in[5];
    float* out = (float*)d_out;

    // 1. ray walk (4 depth-chunks per ray) -> run list + touched bitmap
    run_kernel<<<RUN_BLOCKS, 256>>>(rots, intrins, post_rots, trans, post_trans);

    // 2. feature accumulate into channel-last scratch (coalesced vector reds)
    scatter_runs_kernel<<<NWARPS2 * BLKS_PER_SEG, 256>>>(x);

    // 3. write output (zeros + gather), restore scratch/bitmap invariants
    out_write_kernel<<<dim3(WORDS_PER_B, BB), 256>>>(out);
}